// round 1
// baseline (speedup 1.0000x reference)
#include <cuda_runtime.h>

// VoxelGrid trilinear interpolation.
// Inputs (metadata order):
//   d_in[0]: x    float32 [N, 3]           (N = 8388608)
//   d_in[1]: grid float32 [200, 200, 50, 1]
// Output: (sigma, alpha) -> out_size = 2*N floats: out[0:N]=sigma, out[N:2N]=alpha(=0)
//
// Grid constants: LOWER=(-4,-4,-1), RESOLUTION=25, SIZE=(200,200,50)
// idx = (x - LOWER)*25 ; valid iff idx in [0, size-1] per axis (inclusive).

#define SX 200
#define SY 200
#define SZ 50
#define STRIDE_X (SY * SZ)   // 10000
#define STRIDE_Y (SZ)        // 50

__global__ __launch_bounds__(256)
void voxelgrid_kernel(const float* __restrict__ x,
                      const float* __restrict__ grid,
                      float* __restrict__ out,
                      int n)
{
    const int t = blockIdx.x * blockDim.x + threadIdx.x;
    const long long base = (long long)t * 4;
    if (base >= n) return;

    // Load 4 points = 12 contiguous floats via 3 x float4 (fully coalesced).
    const float4* xv = reinterpret_cast<const float4*>(x + base * 3);
    const float4 va = xv[0];
    const float4 vb = xv[1];
    const float4 vc = xv[2];

    float px[4] = {va.x, va.w, vb.z, vc.y};
    float py[4] = {va.y, vb.x, vb.w, vc.z};
    float pz[4] = {va.z, vb.y, vc.x, vc.w};

    float sig[4];

    #pragma unroll
    for (int p = 0; p < 4; ++p) {
        const float ix = (px[p] + 4.0f) * 25.0f;
        const float iy = (py[p] + 4.0f) * 25.0f;
        const float iz = (pz[p] + 1.0f) * 25.0f;

        const bool valid =
            (ix >= 0.0f) & (ix <= (float)(SX - 1)) &
            (iy >= 0.0f) & (iy <= (float)(SY - 1)) &
            (iz >= 0.0f) & (iz <= (float)(SZ - 1));

        const float fx = floorf(ix);
        const float fy = floorf(iy);
        const float fz = floorf(iz);

        int x0 = min(max((int)fx, 0), SX - 1);
        int y0 = min(max((int)fy, 0), SY - 1);
        int z0 = min(max((int)fz, 0), SZ - 1);
        const int x1 = min(x0 + 1, SX - 1);
        const int y1 = min(y0 + 1, SY - 1);
        const int z1 = min(z0 + 1, SZ - 1);

        const float tx = ix - fx;
        const float ty = iy - fy;
        const float tz = iz - fz;
        const float sx0 = 1.0f - tx, sy0 = 1.0f - ty, sz0 = 1.0f - tz;

        const int bx0 = x0 * STRIDE_X;
        const int bx1 = x1 * STRIDE_X;
        const int by0 = y0 * STRIDE_Y;
        const int by1 = y1 * STRIDE_Y;

        // 8 gathers — issue all loads before consuming (MLP).
        const float v000 = __ldg(grid + bx0 + by0 + z0);
        const float v001 = __ldg(grid + bx0 + by0 + z1);
        const float v010 = __ldg(grid + bx0 + by1 + z0);
        const float v011 = __ldg(grid + bx0 + by1 + z1);
        const float v100 = __ldg(grid + bx1 + by0 + z0);
        const float v101 = __ldg(grid + bx1 + by0 + z1);
        const float v110 = __ldg(grid + bx1 + by1 + z0);
        const float v111 = __ldg(grid + bx1 + by1 + z1);

        // Weighted-sum form matching the reference (8 corner products).
        float acc;
        acc = v000 * (sx0 * sy0 * sz0);
        acc = fmaf(v001, sx0 * sy0 * tz,  acc);
        acc = fmaf(v010, sx0 * ty  * sz0, acc);
        acc = fmaf(v011, sx0 * ty  * tz,  acc);
        acc = fmaf(v100, tx  * sy0 * sz0, acc);
        acc = fmaf(v101, tx  * sy0 * tz,  acc);
        acc = fmaf(v110, tx  * ty  * sz0, acc);
        acc = fmaf(v111, tx  * ty  * tz,  acc);

        sig[p] = valid ? acc : 0.0f;
    }

    // Coalesced float4 stores: sigma then alpha(=0).
    float4* so = reinterpret_cast<float4*>(out + base);
    *so = make_float4(sig[0], sig[1], sig[2], sig[3]);
    float4* ao = reinterpret_cast<float4*>(out + (long long)n + base);
    *ao = make_float4(0.0f, 0.0f, 0.0f, 0.0f);
}

extern "C" void kernel_launch(void* const* d_in, const int* in_sizes, int n_in,
                              void* d_out, int out_size)
{
    const float* x    = (const float*)d_in[0];
    const float* grid = (const float*)d_in[1];
    float* out = (float*)d_out;

    const int n = in_sizes[0] / 3;          // number of points
    const int threads = 256;
    const int pts_per_thread = 4;
    const int blocks = (n + threads * pts_per_thread - 1) / (threads * pts_per_thread);

    voxelgrid_kernel<<<blocks, threads>>>(x, grid, out, n);
}

// round 2
// speedup vs baseline: 2.2266x; 2.2266x over previous
#include <cuda_runtime.h>

// VoxelGrid trilinear interpolation, corner-packed.
//
// Stage 1 (pack): P[x][y][z] = float4( g[x][y][z], g[x][y][z1],
//                                      g[x][y1][z], g[x][y1][z1] )
//   with y1=min(y+1,SY-1), z1=min(z+1,SZ-1).  32 MB __device__ scratch.
// Stage 2 (query): per point only 2 aligned LDG.128 gathers (x0, x1 cells)
//   instead of 8 scalar gathers -> 4x fewer L1tex wavefronts + L2 sectors.
//
// Inputs: d_in[0]=x float32[N,3], d_in[1]=grid float32[200,200,50,1]
// Output: out[0:N]=sigma, out[N:2N]=alpha(=0)

#define SX 200
#define SY 200
#define SZ 50
#define NCELLS (SX * SY * SZ)     // 2,000,000
#define STRIDE_X (SY * SZ)        // 10000
#define STRIDE_Y (SZ)             // 50

__device__ float4 g_packed[NCELLS];   // 32 MB static scratch (allowed)

__global__ __launch_bounds__(256)
void pack_kernel(const float* __restrict__ g)
{
    const int idx = blockIdx.x * blockDim.x + threadIdx.x;
    if (idx >= NCELLS) return;
    const int z = idx % SZ;
    const int y = (idx / SZ) % SY;
    const int x = idx / (SZ * SY);
    const int z1 = min(z + 1, SZ - 1);
    const int y1 = min(y + 1, SY - 1);
    const float* b = g + x * STRIDE_X;
    float4 v;
    v.x = __ldg(b + y  * STRIDE_Y + z);
    v.y = __ldg(b + y  * STRIDE_Y + z1);
    v.z = __ldg(b + y1 * STRIDE_Y + z);
    v.w = __ldg(b + y1 * STRIDE_Y + z1);
    g_packed[idx] = v;
}

__global__ __launch_bounds__(256)
void voxelgrid_kernel(const float* __restrict__ x,
                      float* __restrict__ out,
                      int n)
{
    const int t = blockIdx.x * blockDim.x + threadIdx.x;
    const long long base = (long long)t * 4;
    if (base >= n) return;

    // 4 points = 12 contiguous floats via 3 x float4 (fully coalesced).
    const float4* xv = reinterpret_cast<const float4*>(x + base * 3);
    const float4 va = xv[0];
    const float4 vb = xv[1];
    const float4 vc = xv[2];

    const float px[4] = {va.x, va.w, vb.z, vc.y};
    const float py[4] = {va.y, vb.x, vb.w, vc.z};
    const float pz[4] = {va.z, vb.y, vc.x, vc.w};

    float sig[4];

    #pragma unroll
    for (int p = 0; p < 4; ++p) {
        const float ix = (px[p] + 4.0f) * 25.0f;
        const float iy = (py[p] + 4.0f) * 25.0f;
        const float iz = (pz[p] + 1.0f) * 25.0f;

        const bool valid =
            (ix >= 0.0f) & (ix <= (float)(SX - 1)) &
            (iy >= 0.0f) & (iy <= (float)(SY - 1)) &
            (iz >= 0.0f) & (iz <= (float)(SZ - 1));

        const float fx = floorf(ix);
        const float fy = floorf(iy);
        const float fz = floorf(iz);

        const int x0 = min(max((int)fx, 0), SX - 1);
        const int y0 = min(max((int)fy, 0), SY - 1);
        const int z0 = min(max((int)fz, 0), SZ - 1);
        const int x1 = min(x0 + 1, SX - 1);

        const float tx = ix - fx;
        const float ty = iy - fy;
        const float tz = iz - fz;
        const float sx0 = 1.0f - tx, sy0 = 1.0f - ty, sz0 = 1.0f - tz;

        const int cell = y0 * STRIDE_Y + z0;

        // 2 aligned 16B gathers replace 8 scalar gathers.
        const float4 v0 = __ldg(&g_packed[x0 * STRIDE_X + cell]);
        const float4 v1 = __ldg(&g_packed[x1 * STRIDE_X + cell]);

        const float w00 = sy0 * sz0;
        const float w01 = sy0 * tz;
        const float w10 = ty  * sz0;
        const float w11 = ty  * tz;

        float inner0 = v0.x * w00;
        inner0 = fmaf(v0.y, w01, inner0);
        inner0 = fmaf(v0.z, w10, inner0);
        inner0 = fmaf(v0.w, w11, inner0);

        float inner1 = v1.x * w00;
        inner1 = fmaf(v1.y, w01, inner1);
        inner1 = fmaf(v1.z, w10, inner1);
        inner1 = fmaf(v1.w, w11, inner1);

        const float acc = fmaf(sx0, inner0, tx * inner1);
        sig[p] = valid ? acc : 0.0f;
    }

    float4* so = reinterpret_cast<float4*>(out + base);
    *so = make_float4(sig[0], sig[1], sig[2], sig[3]);
    float4* ao = reinterpret_cast<float4*>(out + (long long)n + base);
    *ao = make_float4(0.0f, 0.0f, 0.0f, 0.0f);
}

extern "C" void kernel_launch(void* const* d_in, const int* in_sizes, int n_in,
                              void* d_out, int out_size)
{
    const float* x    = (const float*)d_in[0];
    const float* grid = (const float*)d_in[1];
    float* out = (float*)d_out;

    const int n = in_sizes[0] / 3;

    const int pack_threads = 256;
    const int pack_blocks = (NCELLS + pack_threads - 1) / pack_threads;
    pack_kernel<<<pack_blocks, pack_threads>>>(grid);

    const int threads = 256;
    const int pts_per_thread = 4;
    const int blocks = (n + threads * pts_per_thread - 1) / (threads * pts_per_thread);
    voxelgrid_kernel<<<blocks, threads>>>(x, out, n);
}

// round 3
// speedup vs baseline: 2.5304x; 1.1364x over previous
#include <cuda_runtime.h>

// VoxelGrid trilinear interpolation, 8-corner packed + 256-bit gathers.
//
// Stage 1 (pack): Cell8[x][y][z] = all 8 trilinear corners of cell (x,y,z),
//   clamped exactly as the reference (i1 = min(i0+1, size-1)). 64 MB scratch.
// Stage 2 (query): ONE aligned 32B gather (ld.global.nc.v8.f32) per point.
//
// Inputs: d_in[0]=x float32[N,3], d_in[1]=grid float32[200,200,50,1]
// Output: out[0:N]=sigma, out[N:2N]=alpha(=0)

#define SX 200
#define SY 200
#define SZ 50
#define NCELLS (SX * SY * SZ)     // 2,000,000
#define STRIDE_X (SY * SZ)        // 10000
#define STRIDE_Y (SZ)             // 50

struct __align__(32) Cell8 {
    float4 a;   // x0 plane: (v000, v001, v010, v011)
    float4 b;   // x1 plane: (v100, v101, v110, v111)
};

__device__ Cell8 g_packed8[NCELLS];   // 64 MB static scratch (allowed)

__global__ __launch_bounds__(256)
void pack_kernel(const float* __restrict__ g)
{
    const int idx = blockIdx.x * blockDim.x + threadIdx.x;
    if (idx >= NCELLS) return;
    const int z = idx % SZ;
    const int y = (idx / SZ) % SY;
    const int x = idx / (SZ * SY);
    const int z1 = min(z + 1, SZ - 1);
    const int y1 = min(y + 1, SY - 1);
    const int x1 = min(x + 1, SX - 1);

    const float* b0 = g + x  * STRIDE_X;
    const float* b1 = g + x1 * STRIDE_X;

    Cell8 c;
    c.a.x = __ldg(b0 + y  * STRIDE_Y + z);
    c.a.y = __ldg(b0 + y  * STRIDE_Y + z1);
    c.a.z = __ldg(b0 + y1 * STRIDE_Y + z);
    c.a.w = __ldg(b0 + y1 * STRIDE_Y + z1);
    c.b.x = __ldg(b1 + y  * STRIDE_Y + z);
    c.b.y = __ldg(b1 + y  * STRIDE_Y + z1);
    c.b.z = __ldg(b1 + y1 * STRIDE_Y + z);
    c.b.w = __ldg(b1 + y1 * STRIDE_Y + z1);
    g_packed8[idx] = c;
}

// One 256-bit non-coherent load with L2 evict_last (keep packed grid resident).
__device__ __forceinline__ void ldg256(const Cell8* p, float4& q0, float4& q1)
{
    asm volatile(
        "ld.global.nc.L2::evict_last.v8.f32 "
        "{%0, %1, %2, %3, %4, %5, %6, %7}, [%8];"
        : "=f"(q0.x), "=f"(q0.y), "=f"(q0.z), "=f"(q0.w),
          "=f"(q1.x), "=f"(q1.y), "=f"(q1.z), "=f"(q1.w)
        : "l"(p));
}

__global__ __launch_bounds__(256)
void voxelgrid_kernel(const float* __restrict__ x,
                      float* __restrict__ out,
                      int n)
{
    const int t = blockIdx.x * blockDim.x + threadIdx.x;
    const long long base = (long long)t * 4;
    if (base >= n) return;

    // 4 points = 12 contiguous floats via 3 x float4 (fully coalesced).
    const float4* xv = reinterpret_cast<const float4*>(x + base * 3);
    const float4 va = xv[0];
    const float4 vb = xv[1];
    const float4 vc = xv[2];

    const float px[4] = {va.x, va.w, vb.z, vc.y};
    const float py[4] = {va.y, vb.x, vb.w, vc.z};
    const float pz[4] = {va.z, vb.y, vc.x, vc.w};

    float sig[4];

    #pragma unroll
    for (int p = 0; p < 4; ++p) {
        const float ix = (px[p] + 4.0f) * 25.0f;
        const float iy = (py[p] + 4.0f) * 25.0f;
        const float iz = (pz[p] + 1.0f) * 25.0f;

        const bool valid =
            (ix >= 0.0f) & (ix <= (float)(SX - 1)) &
            (iy >= 0.0f) & (iy <= (float)(SY - 1)) &
            (iz >= 0.0f) & (iz <= (float)(SZ - 1));

        const float fx = floorf(ix);
        const float fy = floorf(iy);
        const float fz = floorf(iz);

        const int x0 = min(max((int)fx, 0), SX - 1);
        const int y0 = min(max((int)fy, 0), SY - 1);
        const int z0 = min(max((int)fz, 0), SZ - 1);

        const float tx = ix - fx;
        const float ty = iy - fy;
        const float tz = iz - fz;
        const float sx0 = 1.0f - tx, sy0 = 1.0f - ty, sz0 = 1.0f - tz;

        // Single 32B gather: all 8 corners.
        float4 v0, v1;
        ldg256(&g_packed8[x0 * STRIDE_X + y0 * STRIDE_Y + z0], v0, v1);

        const float w00 = sy0 * sz0;
        const float w01 = sy0 * tz;
        const float w10 = ty  * sz0;
        const float w11 = ty  * tz;

        float inner0 = v0.x * w00;
        inner0 = fmaf(v0.y, w01, inner0);
        inner0 = fmaf(v0.z, w10, inner0);
        inner0 = fmaf(v0.w, w11, inner0);

        float inner1 = v1.x * w00;
        inner1 = fmaf(v1.y, w01, inner1);
        inner1 = fmaf(v1.z, w10, inner1);
        inner1 = fmaf(v1.w, w11, inner1);

        const float acc = fmaf(sx0, inner0, tx * inner1);
        sig[p] = valid ? acc : 0.0f;
    }

    // Streaming stores (evict-first): don't pollute L2 against packed grid.
    float4* so = reinterpret_cast<float4*>(out + base);
    __stcs(so, make_float4(sig[0], sig[1], sig[2], sig[3]));
    float4* ao = reinterpret_cast<float4*>(out + (long long)n + base);
    __stcs(ao, make_float4(0.0f, 0.0f, 0.0f, 0.0f));
}

extern "C" void kernel_launch(void* const* d_in, const int* in_sizes, int n_in,
                              void* d_out, int out_size)
{
    const float* x    = (const float*)d_in[0];
    const float* grid = (const float*)d_in[1];
    float* out = (float*)d_out;

    const int n = in_sizes[0] / 3;

    const int pack_threads = 256;
    const int pack_blocks = (NCELLS + pack_threads - 1) / pack_threads;
    pack_kernel<<<pack_blocks, pack_threads>>>(grid);

    const int threads = 256;
    const int pts_per_thread = 4;
    const int blocks = (n + threads * pts_per_thread - 1) / (threads * pts_per_thread);
    voxelgrid_kernel<<<blocks, threads>>>(x, out, n);
}